// round 10
// baseline (speedup 1.0000x reference)
#include <cuda_runtime.h>
#include <cuda_fp16.h>
#include <cuda_bf16.h>

// ResidualGridVolume: out[n,c] = trilinear((base+detail)[c], xyz[n]/1.5), C=28, R=128.
//
// Design (R7, resubmitted after two infra-failed rounds):
// A ~random-access 112-134 MB working set cannot be made L2-resident (R6:
// ~950 MB DRAM churn). Fix the ACCESS ORDER: bucket the 2M points by coarse
// voxel cell (4^3 cells, 32^3 buckets, z-major), then gather in bucket order.
// The sample kernel sweeps the volume in z-slabs (slab working set ~5 MB),
// so the volume is read from DRAM ~once, and points within a warp share
// corner cache lines (fewer L1 wavefronts). Volume: fp16, 64B-padded voxels,
// quad-cooperative gather (4 threads/point, 16B chunks). Each point writes
// only its own output row -> bit-deterministic regardless of atomic
// scatter order.

static constexpr int R    = 128;
static constexpr int R3   = R * R * R;      // 2,097,152 voxels
static constexpr int CH   = 28;             // 1 density + 27 SH
static constexpr int CSB  = 32;             // padded channel stride (halves) = 64 B
static constexpr int NB   = 32 * 32 * 32;   // buckets (4^3-voxel cells)
static constexpr int NCAP = 2 * 1024 * 1024;// max points supported

// Scratch (__device__ globals; no runtime allocation). ~166 MB total.
__device__ __align__(256) __half g_volh[(size_t)R3 * CSB]; // 134 MB
__device__ __align__(256) float4 g_pts[NCAP];              // sorted (x,y,z,bitcast idx)
__device__ int g_cnt[NB];                                  // bucket counts -> offsets

// ---------------------------------------------------------------------------
// Shared coordinate -> cell math (identical in hist & scatter).
// ---------------------------------------------------------------------------
__device__ __forceinline__ void point_cell(float x, float y, float z,
                                           int& x0, int& y0, int& z0) {
    const float inv_bound = 1.0f / 1.5f;
    float px = (x * inv_bound + 1.0f) * 0.5f * 127.0f;
    float py = (y * inv_bound + 1.0f) * 0.5f * 127.0f;
    float pz = (z * inv_bound + 1.0f) * 0.5f * 127.0f;
    x0 = min(max((int)floorf(px), 0), R - 2);
    y0 = min(max((int)floorf(py), 0), R - 2);
    z0 = min(max((int)floorf(pz), 0), R - 2);
}

__device__ __forceinline__ int bucket_of(int x0, int y0, int z0) {
    // z-major so bucket order sweeps volume slabs in memory order.
    return ((z0 >> 2) * 32 + (y0 >> 2)) * 32 + (x0 >> 2);
}

// ---------------------------------------------------------------------------
// Binning pipeline
// ---------------------------------------------------------------------------
__global__ void zero_cnt_kernel() {
    int i = blockIdx.x * blockDim.x + threadIdx.x;
    if (i < NB) g_cnt[i] = 0;
}

__global__ void hist_kernel(const float* __restrict__ xyz, int N) {
    int p = blockIdx.x * blockDim.x + threadIdx.x;
    if (p >= N) return;
    float x = __ldcs(xyz + 3 * p + 0);
    float y = __ldcs(xyz + 3 * p + 1);
    float z = __ldcs(xyz + 3 * p + 2);
    int x0, y0, z0; point_cell(x, y, z, x0, y0, z0);
    atomicAdd(&g_cnt[bucket_of(x0, y0, z0)], 1);
}

// Single-block exclusive scan of g_cnt (NB = 32768 = 1024 threads x 32).
__global__ void scan_kernel() {
    __shared__ int s[1024];
    int t = threadIdx.x;
    int base = t * 32;
    int local[32];
    int sum = 0;
#pragma unroll
    for (int i = 0; i < 32; i++) { local[i] = g_cnt[base + i]; sum += local[i]; }
    s[t] = sum;
    __syncthreads();
    // Hillis-Steele inclusive scan over the 1024 per-thread sums.
    for (int off = 1; off < 1024; off <<= 1) {
        int v = (t >= off) ? s[t - off] : 0;
        __syncthreads();
        s[t] += v;
        __syncthreads();
    }
    int prefix = (t == 0) ? 0 : s[t - 1];  // exclusive prefix for this thread
#pragma unroll
    for (int i = 0; i < 32; i++) { g_cnt[base + i] = prefix; prefix += local[i]; }
}

__global__ void scatter_kernel(const float* __restrict__ xyz, int N) {
    int p = blockIdx.x * blockDim.x + threadIdx.x;
    if (p >= N) return;
    float x = __ldcs(xyz + 3 * p + 0);
    float y = __ldcs(xyz + 3 * p + 1);
    float z = __ldcs(xyz + 3 * p + 2);
    int x0, y0, z0; point_cell(x, y, z, x0, y0, z0);
    int pos = atomicAdd(&g_cnt[bucket_of(x0, y0, z0)], 1);
    __stcs(&g_pts[pos], make_float4(x, y, z, __int_as_float(p)));
}

// ---------------------------------------------------------------------------
// Kernel: fuse base+detail -> fp16, voxel-major, 64B-padded voxels.
// Streaming input reads; normal stores so hot z-slabs persist in L2.
// ---------------------------------------------------------------------------
__global__ void fuse_transpose_kernel(const float* __restrict__ base_density,
                                      const float* __restrict__ base_sh,
                                      const float* __restrict__ detail_density,
                                      const float* __restrict__ detail_sh) {
    int v = blockIdx.x * blockDim.x + threadIdx.x;
    if (v >= R3) return;

    __half h[CSB];
    h[0] = __float2half_rn(__ldcs(base_density + v) + __ldcs(detail_density + v));
#pragma unroll
    for (int c = 0; c < 27; c++) {
        size_t off = (size_t)c * R3 + (size_t)v;
        h[c + 1] = __float2half_rn(__ldcs(base_sh + off) + __ldcs(detail_sh + off));
    }
#pragma unroll
    for (int c = CH; c < CSB; c++) h[c] = __float2half_rn(0.0f);

    uint4* dst = reinterpret_cast<uint4*>(g_volh + (size_t)v * CSB);
#pragma unroll
    for (int i = 0; i < 4; i++)
        dst[i] = reinterpret_cast<const uint4*>(h)[i];
}

// ---------------------------------------------------------------------------
// Kernel: quad-cooperative trilinear gather over SORTED points.
// 4 threads per point; thread j = tid&3 owns 16B chunk j (channels 8j..8j+7).
// ---------------------------------------------------------------------------
__global__ void __launch_bounds__(256)
sample_kernel(float* __restrict__ out, int N) {
    int t = blockIdx.x * blockDim.x + threadIdx.x;
    int i = t >> 2;          // sorted point slot (8 points per warp)
    int j = t & 3;           // chunk index
    if (i >= N) return;

    float4 pt = __ldg(&g_pts[i]);   // quad-broadcast (one 16B chunk per quad)
    int p = __float_as_int(pt.w);   // original point index

    const float inv_bound = 1.0f / 1.5f;
    float px = (pt.x * inv_bound + 1.0f) * 0.5f * 127.0f;
    float py = (pt.y * inv_bound + 1.0f) * 0.5f * 127.0f;
    float pz = (pt.z * inv_bound + 1.0f) * 0.5f * 127.0f;

    float fx0 = floorf(px), fy0 = floorf(py), fz0 = floorf(pz);
    float fx = px - fx0, fy = py - fy0, fz = pz - fz0;

    int x0 = min(max((int)fx0, 0), R - 2);
    int y0 = min(max((int)fy0, 0), R - 2);
    int z0 = min(max((int)fz0, 0), R - 2);

    float wx1 = fx, wx0 = 1.0f - fx;
    float wy1 = fy, wy0 = 1.0f - fy;
    float wz1 = fz, wz0 = 1.0f - fz;

    float w[8];
    w[0] = wz0 * wy0 * wx0;
    w[1] = wz0 * wy0 * wx1;
    w[2] = wz0 * wy1 * wx0;
    w[3] = wz0 * wy1 * wx1;
    w[4] = wz1 * wy0 * wx0;
    w[5] = wz1 * wy0 * wx1;
    w[6] = wz1 * wy1 * wx0;
    w[7] = wz1 * wy1 * wx1;

    const unsigned OX = CSB;               // +1 in x (in halves)
    const unsigned OY = R * CSB;           // +1 in y
    const unsigned OZ = R * R * CSB;       // +1 in z
    unsigned base = (((unsigned)z0 * R + (unsigned)y0) * R + (unsigned)x0) * CSB;

    unsigned offs[8];
    offs[0] = base;
    offs[1] = base + OX;
    offs[2] = base + OY;
    offs[3] = base + OY + OX;
    offs[4] = base + OZ;
    offs[5] = base + OZ + OX;
    offs[6] = base + OZ + OY;
    offs[7] = base + OZ + OY + OX;

    // Issue all 8 corner loads (MLP = 8), then accumulate.
    uint4 q[8];
#pragma unroll
    for (int k = 0; k < 8; k++)
        q[k] = __ldg(reinterpret_cast<const uint4*>(g_volh + (size_t)offs[k]) + j);

    float acc[8];
#pragma unroll
    for (int a = 0; a < 8; a++) acc[a] = 0.0f;

#pragma unroll
    for (int k = 0; k < 8; k++) {
        float wk = w[k];
        const __half2* h2 = reinterpret_cast<const __half2*>(&q[k]);
#pragma unroll
        for (int m = 0; m < 4; m++) {
            float2 f = __half22float2(h2[m]);
            acc[2 * m + 0] = fmaf(wk, f.x, acc[2 * m + 0]);
            acc[2 * m + 1] = fmaf(wk, f.y, acc[2 * m + 1]);
        }
    }

    // Output row = 112 B at out + p*28. Chunk j covers channels 8j..8j+7
    // (j==3: only 24..27). All float4 stores 16B-aligned. Streaming stores.
    float* orow = out + (size_t)p * CH + 8 * j;
    __stcs(reinterpret_cast<float4*>(orow),
           make_float4(acc[0], acc[1], acc[2], acc[3]));
    if (j < 3) {
        __stcs(reinterpret_cast<float4*>(orow + 4),
               make_float4(acc[4], acc[5], acc[6], acc[7]));
    }
}

// ---------------------------------------------------------------------------
// Launch. Inputs in metadata order:
//   [0] xyz (N*3), [1] base_density (128^3), [2] base_sh (27*128^3),
//   [3] detail_density, [4] detail_sh. Output: float32, N*28.
// ---------------------------------------------------------------------------
extern "C" void kernel_launch(void* const* d_in, const int* in_sizes, int n_in,
                              void* d_out, int out_size) {
    const float* xyz            = (const float*)d_in[0];
    const float* base_density   = (const float*)d_in[1];
    const float* base_sh        = (const float*)d_in[2];
    const float* detail_density = (const float*)d_in[3];
    const float* detail_sh      = (const float*)d_in[4];
    float* out = (float*)d_out;

    int N = in_sizes[0] / 3;
    if (N > NCAP) N = NCAP;  // dataset is fixed at 2M; guard only

    int thr = 256;

    zero_cnt_kernel<<<(NB + thr - 1) / thr, thr>>>();
    hist_kernel<<<(N + thr - 1) / thr, thr>>>(xyz, N);
    scan_kernel<<<1, 1024>>>();
    scatter_kernel<<<(N + thr - 1) / thr, thr>>>(xyz, N);

    fuse_transpose_kernel<<<(R3 + thr - 1) / thr, thr>>>(
        base_density, base_sh, detail_density, detail_sh);

    long long total = 4LL * N;  // 4 threads per point
    sample_kernel<<<(int)((total + thr - 1) / thr), thr>>>(out, N);
}

// round 11
// speedup vs baseline: 1.0999x; 1.0999x over previous
#include <cuda_runtime.h>
#include <cuda_fp16.h>
#include <cuda_bf16.h>

// ResidualGridVolume: out[n,c] = trilinear((base+detail)[c], xyz[n]/1.5), C=28, R=128.
//
// R10 learning: explicit point reordering (hist+scan+scatter) costs ~100-150us
// of extra passes -- more than the volume-locality it buys. Dropped.
// This round: R5 design (fp16 64B-padded voxels, quad-cooperative gather,
// best known 252us) + Z-SPLIT: run the sample kernel twice, pass 1 for points
// with z0 in [64,128), pass 2 for z0 in [0,64). Each pass's random-access
// volume footprint is 67 MB = 0.53x L2 -> genuinely resident after compulsory
// misses (R6 showed 0.9x capacity thrashes; half capacity does not).
// Upper half first: the fuse kernel writes z ascending, so high-z slabs are
// still hot in L2 when pass 1 starts. Inactive points early-out after the
// coordinate check (~10-15us overhead per extra pass). No binning kernels.

static constexpr int R    = 128;
static constexpr int R3   = R * R * R;      // 2,097,152 voxels
static constexpr int CH   = 28;             // 1 density + 27 SH
static constexpr int CSB  = 32;             // padded channel stride (halves) = 64 B

// 134 MB scratch: __device__ global (no runtime allocation).
__device__ __align__(256) __half g_volh[(size_t)R3 * CSB];

// ---------------------------------------------------------------------------
// Kernel 1: fuse base+detail -> fp16, voxel-major, 64B-padded voxels.
// Streaming input reads (__ldcs) keep L2 for the volume; normal stores leave
// the (tail of the) volume L2-resident for the first sample pass.
// ---------------------------------------------------------------------------
__global__ void fuse_transpose_kernel(const float* __restrict__ base_density,
                                      const float* __restrict__ base_sh,
                                      const float* __restrict__ detail_density,
                                      const float* __restrict__ detail_sh) {
    int v = blockIdx.x * blockDim.x + threadIdx.x;
    if (v >= R3) return;

    __half h[CSB];
    h[0] = __float2half_rn(__ldcs(base_density + v) + __ldcs(detail_density + v));
#pragma unroll
    for (int c = 0; c < 27; c++) {
        size_t off = (size_t)c * R3 + (size_t)v;
        h[c + 1] = __float2half_rn(__ldcs(base_sh + off) + __ldcs(detail_sh + off));
    }
#pragma unroll
    for (int c = CH; c < CSB; c++) h[c] = __float2half_rn(0.0f);

    uint4* dst = reinterpret_cast<uint4*>(g_volh + (size_t)v * CSB);
#pragma unroll
    for (int i = 0; i < 4; i++)
        dst[i] = reinterpret_cast<const uint4*>(h)[i];
}

// ---------------------------------------------------------------------------
// Kernel 2: quad-cooperative trilinear gather, restricted to a z-slab.
// 4 threads per point; thread j = tid&3 owns 16B chunk j (channels 8j..8j+7).
// Points whose z0 falls outside [zlo, zhi) exit early (their pass handles
// them). Each point is claimed by exactly one pass.
// ---------------------------------------------------------------------------
__global__ void __launch_bounds__(256)
sample_kernel(const float* __restrict__ xyz, float* __restrict__ out, int N,
              int zlo, int zhi) {
    int t = blockIdx.x * blockDim.x + threadIdx.x;
    int p = t >> 2;          // point index (8 points per warp)
    int j = t & 3;           // chunk index
    if (p >= N) return;

    // Quad-broadcast reads of this point's coords.
    const float inv_bound = 1.0f / 1.5f;
    float gx = __ldcs(xyz + 3 * p + 0) * inv_bound;
    float gy = __ldcs(xyz + 3 * p + 1) * inv_bound;
    float gz = __ldcs(xyz + 3 * p + 2) * inv_bound;

    // align_corners=True: pix = (g + 1) * 0.5 * (size - 1)
    float px = (gx + 1.0f) * 0.5f * 127.0f;
    float py = (gy + 1.0f) * 0.5f * 127.0f;
    float pz = (gz + 1.0f) * 0.5f * 127.0f;

    float fx0 = floorf(px), fy0 = floorf(py), fz0 = floorf(pz);

    // Inputs are interior (|g| <= 0.99); clamps are safety only.
    int z0 = min(max((int)fz0, 0), R - 2);
    if (z0 < zlo || z0 >= zhi) return;   // other pass owns this point

    int x0 = min(max((int)fx0, 0), R - 2);
    int y0 = min(max((int)fy0, 0), R - 2);

    float fx = px - fx0, fy = py - fy0, fz = pz - fz0;

    float wx1 = fx, wx0 = 1.0f - fx;
    float wy1 = fy, wy0 = 1.0f - fy;
    float wz1 = fz, wz0 = 1.0f - fz;

    float w[8];
    w[0] = wz0 * wy0 * wx0;
    w[1] = wz0 * wy0 * wx1;
    w[2] = wz0 * wy1 * wx0;
    w[3] = wz0 * wy1 * wx1;
    w[4] = wz1 * wy0 * wx0;
    w[5] = wz1 * wy0 * wx1;
    w[6] = wz1 * wy1 * wx0;
    w[7] = wz1 * wy1 * wx1;

    const unsigned OX = CSB;               // +1 in x (in halves)
    const unsigned OY = R * CSB;           // +1 in y
    const unsigned OZ = R * R * CSB;       // +1 in z
    unsigned base = (((unsigned)z0 * R + (unsigned)y0) * R + (unsigned)x0) * CSB;

    unsigned offs[8];
    offs[0] = base;
    offs[1] = base + OX;
    offs[2] = base + OY;
    offs[3] = base + OY + OX;
    offs[4] = base + OZ;
    offs[5] = base + OZ + OX;
    offs[6] = base + OZ + OY;
    offs[7] = base + OZ + OY + OX;

    // Issue all 8 corner loads (MLP = 8), then accumulate.
    uint4 q[8];
#pragma unroll
    for (int k = 0; k < 8; k++)
        q[k] = __ldg(reinterpret_cast<const uint4*>(g_volh + (size_t)offs[k]) + j);

    float acc[8];
#pragma unroll
    for (int a = 0; a < 8; a++) acc[a] = 0.0f;

#pragma unroll
    for (int k = 0; k < 8; k++) {
        float wk = w[k];
        const __half2* h2 = reinterpret_cast<const __half2*>(&q[k]);
#pragma unroll
        for (int m = 0; m < 4; m++) {
            float2 f = __half22float2(h2[m]);
            acc[2 * m + 0] = fmaf(wk, f.x, acc[2 * m + 0]);
            acc[2 * m + 1] = fmaf(wk, f.y, acc[2 * m + 1]);
        }
    }

    // Output row = 112 B at out + p*28. Chunk j covers channels 8j..8j+7
    // (j==3: only 24..27). All float4 stores 16B-aligned. Streaming stores
    // so output traffic doesn't evict the L2-resident volume half.
    float* orow = out + (size_t)p * CH + 8 * j;
    __stcs(reinterpret_cast<float4*>(orow),
           make_float4(acc[0], acc[1], acc[2], acc[3]));
    if (j < 3) {
        __stcs(reinterpret_cast<float4*>(orow + 4),
               make_float4(acc[4], acc[5], acc[6], acc[7]));
    }
}

// ---------------------------------------------------------------------------
// Launch. Inputs in metadata order:
//   [0] xyz (N*3), [1] base_density (128^3), [2] base_sh (27*128^3),
//   [3] detail_density, [4] detail_sh. Output: float32, N*28.
// ---------------------------------------------------------------------------
extern "C" void kernel_launch(void* const* d_in, const int* in_sizes, int n_in,
                              void* d_out, int out_size) {
    const float* xyz            = (const float*)d_in[0];
    const float* base_density   = (const float*)d_in[1];
    const float* base_sh        = (const float*)d_in[2];
    const float* detail_density = (const float*)d_in[3];
    const float* detail_sh      = (const float*)d_in[4];
    float* out = (float*)d_out;

    int N = in_sizes[0] / 3;
    int thr = 256;

    fuse_transpose_kernel<<<(R3 + thr - 1) / thr, thr>>>(
        base_density, base_sh, detail_density, detail_sh);

    long long total = 4LL * N;  // 4 threads per point
    int blocks = (int)((total + thr - 1) / thr);
    // Upper half first (hot in L2 from fuse's ascending-z writes), then lower.
    sample_kernel<<<blocks, thr>>>(xyz, out, N, 64, 128);
    sample_kernel<<<blocks, thr>>>(xyz, out, N, 0, 64);
}

// round 13
// speedup vs baseline: 1.2625x; 1.1478x over previous
#include <cuda_runtime.h>
#include <cuda_fp16.h>
#include <cuda_bf16.h>

// ResidualGridVolume: out[n,c] = trilinear((base+detail)[c], xyz[n]/1.5), C=28, R=128.
//
// R10/R11 learning: extra passes over the 2M-point list (binning OR z-split)
// always lose. Must be single-pass over points. R6 learning: the 112 MB
// unpadded fp16 volume FITS in L2 (126 MB) but thrashes under default
// replacement against streaming output traffic. Fix the REPLACEMENT POLICY:
// L2 evict_last policy (via createpolicy + L2::cache_hint -- sm_103a ptxas
// rejects the bare .L2::evict_last modifier on <32B accesses) on volume
// stores (fuse) and volume loads (sample); output/xyz use evict-first (.cs).
// Gather: oct-cooperative (8 thr/pt, thread j<7 owns channels 4j..4j+3 via
// one 8B-aligned uint2 per corner).

static constexpr int R   = 128;
static constexpr int R3  = R * R * R;     // 2,097,152 voxels
static constexpr int CH  = 28;            // 1 density + 27 SH (56 B fp16/voxel)

// 112 MB scratch (+pad): __device__ global (no runtime allocation).
__device__ __align__(256) __half g_volh[(size_t)R3 * CH + 64];

// ---- L2 eviction-priority helpers (createpolicy + cache_hint form) --------
__device__ __forceinline__ unsigned long long evict_last_policy() {
    unsigned long long pol;
    asm("createpolicy.fractional.L2::evict_last.b64 %0, 1.0;" : "=l"(pol));
    return pol;
}
__device__ __forceinline__ uint2 ldg_nc_el_u2(const __half* p,
                                              unsigned long long pol) {
    uint2 v;
    asm volatile("ld.global.nc.L2::cache_hint.v2.u32 {%0,%1}, [%2], %3;"
                 : "=r"(v.x), "=r"(v.y) : "l"(p), "l"(pol));
    return v;
}
__device__ __forceinline__ void stg_el_u2(__half* p, uint2 v,
                                          unsigned long long pol) {
    asm volatile("st.global.L2::cache_hint.v2.u32 [%0], {%1,%2}, %3;"
                 :: "l"(p), "r"(v.x), "r"(v.y), "l"(pol) : "memory");
}

// ---------------------------------------------------------------------------
// Kernel 1: fuse base+detail -> fp16, voxel-major, 56 B voxels (no padding).
// Streaming input reads (__ldcs); evict_last stores make the volume sticky
// in L2 so the sample kernel finds it resident.
// ---------------------------------------------------------------------------
__global__ void fuse_transpose_kernel(const float* __restrict__ base_density,
                                      const float* __restrict__ base_sh,
                                      const float* __restrict__ detail_density,
                                      const float* __restrict__ detail_sh) {
    int v = blockIdx.x * blockDim.x + threadIdx.x;
    if (v >= R3) return;

    __half h[CH];
    h[0] = __float2half_rn(__ldcs(base_density + v) + __ldcs(detail_density + v));
#pragma unroll
    for (int c = 0; c < 27; c++) {
        size_t off = (size_t)c * R3 + (size_t)v;
        h[c + 1] = __float2half_rn(__ldcs(base_sh + off) + __ldcs(detail_sh + off));
    }

    unsigned long long pol = evict_last_policy();
    __half* dst = g_volh + (size_t)v * CH;
    const uint2* src = reinterpret_cast<const uint2*>(h);
#pragma unroll
    for (int i = 0; i < 7; i++)
        stg_el_u2(dst + 4 * i, src[i], pol);
}

// ---------------------------------------------------------------------------
// Kernel 2: oct-cooperative trilinear gather. 8 threads per point; thread
// j = tid&7 (j<7) owns channels 4j..4j+3 via one uint2 per corner, loaded
// with evict_last policy so the volume stays resident against streaming
// output traffic.
// ---------------------------------------------------------------------------
__global__ void __launch_bounds__(256)
sample_kernel(const float* __restrict__ xyz, float* __restrict__ out, int N) {
    int t = blockIdx.x * blockDim.x + threadIdx.x;
    int p = t >> 3;          // point index (4 points per warp)
    int j = t & 7;           // chunk index; j==7 idles through the loads
    if (p >= N) return;

    // Oct-broadcast reads of this point's coords.
    const float inv_bound = 1.0f / 1.5f;
    float gx = __ldcs(xyz + 3 * p + 0) * inv_bound;
    float gy = __ldcs(xyz + 3 * p + 1) * inv_bound;
    float gz = __ldcs(xyz + 3 * p + 2) * inv_bound;

    // align_corners=True: pix = (g + 1) * 0.5 * (size - 1)
    float px = (gx + 1.0f) * 0.5f * 127.0f;
    float py = (gy + 1.0f) * 0.5f * 127.0f;
    float pz = (gz + 1.0f) * 0.5f * 127.0f;

    float fx0 = floorf(px), fy0 = floorf(py), fz0 = floorf(pz);
    float fx = px - fx0, fy = py - fy0, fz = pz - fz0;

    // Inputs are interior (|g| <= 0.99); clamps are safety only.
    int x0 = min(max((int)fx0, 0), R - 2);
    int y0 = min(max((int)fy0, 0), R - 2);
    int z0 = min(max((int)fz0, 0), R - 2);

    float wx1 = fx, wx0 = 1.0f - fx;
    float wy1 = fy, wy0 = 1.0f - fy;
    float wz1 = fz, wz0 = 1.0f - fz;

    float w[8];
    w[0] = wz0 * wy0 * wx0;
    w[1] = wz0 * wy0 * wx1;
    w[2] = wz0 * wy1 * wx0;
    w[3] = wz0 * wy1 * wx1;
    w[4] = wz1 * wy0 * wx0;
    w[5] = wz1 * wy0 * wx1;
    w[6] = wz1 * wy1 * wx0;
    w[7] = wz1 * wy1 * wx1;

    const unsigned OX = CH;               // +1 in x (in halves)
    const unsigned OY = R * CH;           // +1 in y
    const unsigned OZ = R * R * CH;       // +1 in z
    unsigned base = (((unsigned)z0 * R + (unsigned)y0) * R + (unsigned)x0) * CH
                    + 4u * (unsigned)(j < 7 ? j : 0);  // j==7 aliases chunk 0

    unsigned offs[8];
    offs[0] = base;
    offs[1] = base + OX;
    offs[2] = base + OY;
    offs[3] = base + OY + OX;
    offs[4] = base + OZ;
    offs[5] = base + OZ + OX;
    offs[6] = base + OZ + OY;
    offs[7] = base + OZ + OY + OX;

    unsigned long long pol = evict_last_policy();

    // Issue all 8 corner loads (MLP = 8), then accumulate.
    uint2 q[8];
#pragma unroll
    for (int k = 0; k < 8; k++)
        q[k] = ldg_nc_el_u2(g_volh + (size_t)offs[k], pol);

    float acc0 = 0.f, acc1 = 0.f, acc2 = 0.f, acc3 = 0.f;
#pragma unroll
    for (int k = 0; k < 8; k++) {
        float wk = w[k];
        __half2 h0 = *reinterpret_cast<__half2*>(&q[k].x);
        __half2 h1 = *reinterpret_cast<__half2*>(&q[k].y);
        float2 f0 = __half22float2(h0);
        float2 f1 = __half22float2(h1);
        acc0 = fmaf(wk, f0.x, acc0);
        acc1 = fmaf(wk, f0.y, acc1);
        acc2 = fmaf(wk, f1.x, acc2);
        acc3 = fmaf(wk, f1.y, acc3);
    }

    // Output row = 112 B; thread j stores bytes [16j, 16j+16) of row p.
    // Always 16B-aligned. Streaming (evict-first): don't displace the volume.
    if (j < 7) {
        float4* o = reinterpret_cast<float4*>(out + (size_t)p * CH + 4 * j);
        __stcs(o, make_float4(acc0, acc1, acc2, acc3));
    }
}

// ---------------------------------------------------------------------------
// Launch. Inputs in metadata order:
//   [0] xyz (N*3), [1] base_density (128^3), [2] base_sh (27*128^3),
//   [3] detail_density, [4] detail_sh. Output: float32, N*28.
// ---------------------------------------------------------------------------
extern "C" void kernel_launch(void* const* d_in, const int* in_sizes, int n_in,
                              void* d_out, int out_size) {
    const float* xyz            = (const float*)d_in[0];
    const float* base_density   = (const float*)d_in[1];
    const float* base_sh        = (const float*)d_in[2];
    const float* detail_density = (const float*)d_in[3];
    const float* detail_sh      = (const float*)d_in[4];
    float* out = (float*)d_out;

    int N = in_sizes[0] / 3;
    int thr = 256;

    fuse_transpose_kernel<<<(R3 + thr - 1) / thr, thr>>>(
        base_density, base_sh, detail_density, detail_sh);

    long long total = 8LL * N;   // 8 threads per point
    int blocks = (int)((total + thr - 1) / thr);
    sample_kernel<<<blocks, thr>>>(xyz, out, N);
}